// round 16
// baseline (speedup 1.0000x reference)
#include <cuda_runtime.h>
#include <cuda_bf16.h>
#include <math.h>
#include <stdint.h>

#define N_NODES 100000
#define N_EDGES 640000

// ---------------- device scratch ----------------
__device__ float g_t[N_NODES * 128];            // GEMM output (pre-aggregation)
__device__ __nv_bfloat16 g_hi[N_NODES * 128];   // activation hi
__device__ __nv_bfloat16 g_lo[N_NODES * 128];   // activation lo
__device__ int   g_cnt[N_NODES];
__device__ int   g_fill[N_NODES];
__device__ float g_dinv[N_NODES];
__device__ int   g_rowptr[N_NODES + 1];
__device__ int   g_bsum[128];
__device__ int   g_eidx[N_EDGES];
__device__ float g_enorm[N_EDGES];
__device__ __nv_bfloat16 g_whi[3 * 128 * 128];  // W1..W3 transposed hi  [n][k]
__device__ __nv_bfloat16 g_wlo[3 * 128 * 128];  // W1..W3 transposed lo  [n][k]
__device__ __nv_bfloat16 g_w4hi[64 * 128];      // W4 transposed+padded hi [n][k]
__device__ __nv_bfloat16 g_w4lo[64 * 128];      // W4 transposed+padded lo [n][k]

__device__ __forceinline__ uint32_t s2u(const void* p) {
    uint32_t a;
    asm("{ .reg .u64 t; cvta.to.shared.u64 t, %1; cvt.u32.u64 %0, t; }" : "=r"(a) : "l"(p));
    return a;
}

// ---------------- prep kernels ----------------
__global__ void k_zero() {
    int i = blockIdx.x * blockDim.x + threadIdx.x;
    if (i < N_NODES) { g_cnt[i] = 0; g_fill[i] = 0; }
}
__global__ void k_count(const int* __restrict__ dst) {
    int e = blockIdx.x * blockDim.x + threadIdx.x;
    if (e < N_EDGES) atomicAdd(&g_cnt[dst[e]], 1);
}

// multi-block scan; also computes dinv
__global__ __launch_bounds__(1024) void k_scan1() {
    int tid = threadIdx.x;
    int i = blockIdx.x * 1024 + tid;
    int v = (i < N_NODES) ? g_cnt[i] : 0;
    if (i < N_NODES) g_dinv[i] = rsqrtf((float)(v + 1));
    int lane = tid & 31, w = tid >> 5;
    int x = v;
    #pragma unroll
    for (int off = 1; off < 32; off <<= 1) {
        int t = __shfl_up_sync(0xFFFFFFFFu, x, off);
        if (lane >= off) x += t;
    }
    __shared__ int ws[32];
    if (lane == 31) ws[w] = x;
    __syncthreads();
    if (w == 0) {
        int y = ws[lane], o = y;
        #pragma unroll
        for (int off = 1; off < 32; off <<= 1) {
            int t = __shfl_up_sync(0xFFFFFFFFu, y, off);
            if (lane >= off) y += t;
        }
        ws[lane] = y - o;
    }
    __syncthreads();
    int incl = x + ws[w];
    if (i < N_NODES) g_rowptr[i] = incl - v;
    if (tid == 1023) g_bsum[blockIdx.x] = incl;
}
__global__ void k_scan2() {
    int tid = threadIdx.x;  // 128
    int v = (tid < 98) ? g_bsum[tid] : 0;
    int lane = tid & 31, w = tid >> 5;
    int x = v;
    #pragma unroll
    for (int off = 1; off < 32; off <<= 1) {
        int t = __shfl_up_sync(0xFFFFFFFFu, x, off);
        if (lane >= off) x += t;
    }
    __shared__ int ws[4];
    if (lane == 31) ws[w] = x;
    __syncthreads();
    __shared__ int wo[4];
    if (tid == 0) { int s = 0; for (int k = 0; k < 4; k++) { wo[k] = s; s += ws[k]; } }
    __syncthreads();
    if (tid < 98) g_bsum[tid] = x - v + wo[w];
}
__global__ void k_scan3() {
    int i = blockIdx.x * blockDim.x + threadIdx.x;
    if (i < N_NODES) g_rowptr[i] += g_bsum[i >> 10];
    if (i == 0) g_rowptr[N_NODES] = N_EDGES;
}
__global__ void k_scatter(const int* __restrict__ src, const int* __restrict__ dst) {
    int e = blockIdx.x * blockDim.x + threadIdx.x;
    if (e >= N_EDGES) return;
    int s = src[e], d = dst[e];
    int pos = g_rowptr[d] + atomicAdd(&g_fill[d], 1);
    g_eidx[pos] = s;
    g_enorm[pos] = g_dinv[s] * g_dinv[d];
}

// ---------------- precision-split conversion ----------------
__global__ void k_convx(const float* __restrict__ x) {
    int i = blockIdx.x * blockDim.x + threadIdx.x;
    if (i >= N_NODES * 32) return;
    float4 v = ((const float4*)x)[i];
    __nv_bfloat16 h0 = __float2bfloat16(v.x), h1 = __float2bfloat16(v.y);
    __nv_bfloat16 h2 = __float2bfloat16(v.z), h3 = __float2bfloat16(v.w);
    __nv_bfloat16 l0 = __float2bfloat16(v.x - __bfloat162float(h0));
    __nv_bfloat16 l1 = __float2bfloat16(v.y - __bfloat162float(h1));
    __nv_bfloat16 l2 = __float2bfloat16(v.z - __bfloat162float(h2));
    __nv_bfloat16 l3 = __float2bfloat16(v.w - __bfloat162float(h3));
    __nv_bfloat162* hp = (__nv_bfloat162*)g_hi;
    __nv_bfloat162* lp = (__nv_bfloat162*)g_lo;
    __nv_bfloat162 a; a.x = h0; a.y = h1; hp[i * 2] = a;
    __nv_bfloat162 b; b.x = h2; b.y = h3; hp[i * 2 + 1] = b;
    __nv_bfloat162 c; c.x = l0; c.y = l1; lp[i * 2] = c;
    __nv_bfloat162 d; d.x = l2; d.y = l3; lp[i * 2 + 1] = d;
}
// W [128k,128n] fp32 -> transposed [n][k] bf16 hi/lo
__global__ void k_convw(const float* __restrict__ W, __nv_bfloat16* __restrict__ hi,
                        __nv_bfloat16* __restrict__ lo) {
    int i = blockIdx.x * blockDim.x + threadIdx.x;  // 16384
    int n = i >> 7, k = i & 127;
    float v = W[k * 128 + n];
    __nv_bfloat16 h = __float2bfloat16(v);
    hi[i] = h;
    lo[i] = __float2bfloat16(v - __bfloat162float(h));
}
// W4 [128k,40n] fp32 -> transposed+padded [64 n][128 k] bf16 hi/lo
__global__ void k_convw4(const float* __restrict__ W) {
    int i = blockIdx.x * blockDim.x + threadIdx.x;  // 8192
    if (i >= 64 * 128) return;
    int n = i >> 7, k = i & 127;
    float v = (n < 40) ? W[k * 40 + n] : 0.f;
    __nv_bfloat16 h = __float2bfloat16(v);
    g_w4hi[i] = h;
    g_w4lo[i] = __float2bfloat16(v - __bfloat162float(h));
}

// ---------------- shared HMMA machinery ----------------
#define TSTRIDE 272

__device__ __forceinline__ void cp16(uint32_t saddr, const void* g) {
    asm volatile("cp.async.cg.shared.global [%0], [%1], 16;" :: "r"(saddr), "l"(g));
}
#define CP_COMMIT() asm volatile("cp.async.commit_group;" ::: "memory")
#define CP_WAIT0()  asm volatile("cp.async.wait_group 0;" ::: "memory")

#define LDSM_X4(r0, r1, r2, r3, addr) \
    asm volatile("ldmatrix.sync.aligned.m8n8.x4.shared.b16 {%0,%1,%2,%3}, [%4];" \
                 : "=r"(r0), "=r"(r1), "=r"(r2), "=r"(r3) : "r"(addr))

#define MMA16816(d, a, b0, b1) \
    asm volatile("mma.sync.aligned.m16n8k16.row.col.f32.bf16.bf16.f32 " \
                 "{%0,%1,%2,%3}, {%4,%5,%6,%7}, {%8,%9}, {%0,%1,%2,%3};" \
                 : "+f"((d)[0]), "+f"((d)[1]), "+f"((d)[2]), "+f"((d)[3]) \
                 : "r"((a)[0]), "r"((a)[1]), "r"((a)[2]), "r"((a)[3]), \
                   "r"(b0), "r"(b1))

// ---------------- persistent HMMA GEMM: [n,128]x[128,128], bf16 hi/lo split ----------
#define PW_HI 0
#define PW_LO 34816
#define PA_BASE 69632
#define PA_HI(b) (PA_BASE + (b) * 34816)
#define PA_LO(b) (PA_BASE + (b) * 34816 + 17408)
#define SM_TOTAL (PA_BASE + 2 * 34816)   // 139264 B

__device__ __forceinline__ void fill_A64(
    uint32_t sb, int buf, const __nv_bfloat16* Ahi, const __nv_bfloat16* Alo,
    int r0, int n, int tid)
{
    uint32_t bh = sb + PA_HI(buf), bl = sb + PA_LO(buf);
    #pragma unroll
    for (int l = 0; l < 4; l++) {
        int idx = tid + l * 256;
        int r = idx >> 4;
        int c = (idx & 15) << 4;
        int gr = r0 + r;
        if (gr >= n) gr = n - 1;
        int so = r * TSTRIDE + c;
        cp16(bh + so, (const char*)Ahi + (size_t)gr * 256 + c);
        cp16(bl + so, (const char*)Alo + (size_t)gr * 256 + c);
    }
}

__global__ __launch_bounds__(256) void gemm_pers(
    const __nv_bfloat16* __restrict__ Ahi, const __nv_bfloat16* __restrict__ Alo,
    const __nv_bfloat16* __restrict__ Whi, const __nv_bfloat16* __restrict__ Wlo,
    float* __restrict__ out, int n)
{
    extern __shared__ char smem[];
    const uint32_t sb = s2u(smem);
    const int tid = threadIdx.x;
    const int lane = tid & 31;
    const int wid = tid >> 5;
    const int wm = wid & 1;
    const int wn = wid >> 1;
    const int ntiles = (n + 63) >> 6;

    #pragma unroll
    for (int l = 0; l < 8; l++) {
        int idx = tid + l * 256;
        int r = idx >> 4;
        int c = (idx & 15) << 4;
        int so = r * TSTRIDE + c;
        cp16(sb + PW_HI + so, (const char*)Whi + (size_t)r * 256 + c);
        cp16(sb + PW_LO + so, (const char*)Wlo + (size_t)r * 256 + c);
    }
    int tile = blockIdx.x;
    if (tile < ntiles) fill_A64(sb, 0, Ahi, Alo, tile * 64, n, tid);
    CP_COMMIT();

    const int rA  = (lane & 7) + (((lane >> 3) & 1) << 3);
    const int kA8 = (lane >> 4) << 4;
    const int rBrow = (lane & 7) + ((lane >> 4) << 4);
    const int kB8   = (((lane >> 3) & 1) << 4);

    const uint32_t aRowRel = (uint32_t)((wm * 32 + rA) * TSTRIDE + kA8);
    uint32_t bRow[2];
    #pragma unroll
    for (int j = 0; j < 2; j++)
        bRow[j] = (uint32_t)((wn * 32 + j * 8 + rBrow) * TSTRIDE + kB8);
    const int colBase = wn * 32 + (lane & 3) * 2;

    int buf = 0;
    for (; tile < ntiles; tile += gridDim.x) {
        CP_WAIT0();
        __syncthreads();
        int next = tile + gridDim.x;
        if (next < ntiles) fill_A64(sb, buf ^ 1, Ahi, Alo, next * 64, n, tid);
        CP_COMMIT();

        float acc[2][2][2][4];
        #pragma unroll
        for (int mt = 0; mt < 2; mt++)
            #pragma unroll
            for (int j = 0; j < 2; j++)
                #pragma unroll
                for (int h = 0; h < 2; h++)
                    #pragma unroll
                    for (int q = 0; q < 4; q++) acc[mt][j][h][q] = 0.f;

        #pragma unroll
        for (int p = 0; p < 3; p++) {
            const uint32_t aOff = sb + ((p == 1) ? PA_LO(buf) : PA_HI(buf));
            const uint32_t wOff = sb + ((p == 2) ? PW_LO : PW_HI);
            #pragma unroll
            for (int ks = 0; ks < 8; ks++) {
                const uint32_t kb = (uint32_t)(ks * 32);
                uint32_t a0[4], a1[4];
                LDSM_X4(a0[0], a0[1], a0[2], a0[3], aOff + aRowRel + kb);
                LDSM_X4(a1[0], a1[1], a1[2], a1[3], aOff + aRowRel + 16 * TSTRIDE + kb);
                uint32_t b[2][4];
                #pragma unroll
                for (int j = 0; j < 2; j++)
                    LDSM_X4(b[j][0], b[j][1], b[j][2], b[j][3], wOff + bRow[j] + kb);
                #pragma unroll
                for (int j = 0; j < 2; j++) {
                    MMA16816(acc[0][j][0], a0, b[j][0], b[j][1]);
                    MMA16816(acc[1][j][0], a1, b[j][0], b[j][1]);
                    MMA16816(acc[0][j][1], a0, b[j][2], b[j][3]);
                    MMA16816(acc[1][j][1], a1, b[j][2], b[j][3]);
                }
            }
        }

        const int r0 = tile * 64;
        #pragma unroll
        for (int mt = 0; mt < 2; mt++) {
            int row = r0 + wm * 32 + mt * 16 + (lane >> 2);
            #pragma unroll
            for (int j = 0; j < 2; j++)
                #pragma unroll
                for (int h = 0; h < 2; h++) {
                    int col = colBase + j * 8 + h * 16;
                    if (row < n)
                        *(float2*)&out[(size_t)row * 128 + col] =
                            make_float2(acc[mt][j][h][0], acc[mt][j][h][1]);
                    if (row + 8 < n)
                        *(float2*)&out[(size_t)(row + 8) * 128 + col] =
                            make_float2(acc[mt][j][h][2], acc[mt][j][h][3]);
                }
        }
        buf ^= 1;
    }
}

// ---------------- persistent HMMA GEMM: [n,128]x[128,64(pad of 40)] ----------------
#define P4W_HI 0
#define P4W_LO 17408
#define P4A_BASE 34816
#define P4A_HI(b) (P4A_BASE + (b) * 69632)
#define P4A_LO(b) (P4A_BASE + (b) * 69632 + 34816)
#define SM40_TOTAL (P4A_BASE + 2 * 69632)   // 174080 B

__device__ __forceinline__ void fill_A128(
    uint32_t sb, int buf, const __nv_bfloat16* Ahi, const __nv_bfloat16* Alo,
    int r0, int n, int tid)
{
    uint32_t bh = sb + P4A_HI(buf), bl = sb + P4A_LO(buf);
    #pragma unroll
    for (int l = 0; l < 8; l++) {
        int idx = tid + l * 256;
        int r = idx >> 4;
        int c = (idx & 15) << 4;
        int gr = r0 + r;
        if (gr >= n) gr = n - 1;
        int so = r * TSTRIDE + c;
        cp16(bh + so, (const char*)Ahi + (size_t)gr * 256 + c);
        cp16(bl + so, (const char*)Alo + (size_t)gr * 256 + c);
    }
}

__global__ __launch_bounds__(256) void gemm40_mma(
    const __nv_bfloat16* __restrict__ Ahi, const __nv_bfloat16* __restrict__ Alo,
    float* __restrict__ out, int n)
{
    extern __shared__ char smem[];
    const uint32_t sb = s2u(smem);
    const int tid = threadIdx.x;
    const int lane = tid & 31;
    const int wid = tid >> 5;
    const int wm = wid & 3;
    const int wn = wid >> 2;
    const int ntiles = (n + 127) >> 7;

    #pragma unroll
    for (int l = 0; l < 4; l++) {
        int idx = tid + l * 256;
        int r = idx >> 4;
        int c = (idx & 15) << 4;
        int so = r * TSTRIDE + c;
        cp16(sb + P4W_HI + so, (const char*)g_w4hi + (size_t)r * 256 + c);
        cp16(sb + P4W_LO + so, (const char*)g_w4lo + (size_t)r * 256 + c);
    }
    int tile = blockIdx.x;
    if (tile < ntiles) fill_A128(sb, 0, Ahi, Alo, tile * 128, n, tid);
    CP_COMMIT();

    const int rA  = (lane & 7) + (((lane >> 3) & 1) << 3);
    const int kA8 = (lane >> 4) << 4;
    const int rBrow = (lane & 7) + ((lane >> 4) << 4);
    const int kB8   = (((lane >> 3) & 1) << 4);

    const uint32_t aRowRel = (uint32_t)((wm * 32 + rA) * TSTRIDE + kA8);
    uint32_t bRow[2];
    #pragma unroll
    for (int j = 0; j < 2; j++)
        bRow[j] = (uint32_t)((wn * 32 + j * 8 + rBrow) * TSTRIDE + kB8);
    const int colBase = wn * 32 + (lane & 3) * 2;

    int buf = 0;
    for (; tile < ntiles; tile += gridDim.x) {
        CP_WAIT0();
        __syncthreads();
        int next = tile + gridDim.x;
        if (next < ntiles) fill_A128(sb, buf ^ 1, Ahi, Alo, next * 128, n, tid);
        CP_COMMIT();

        float acc[2][2][2][4];
        #pragma unroll
        for (int mt = 0; mt < 2; mt++)
            #pragma unroll
            for (int j = 0; j < 2; j++)
                #pragma unroll
                for (int h = 0; h < 2; h++)
                    #pragma unroll
                    for (int q = 0; q < 4; q++) acc[mt][j][h][q] = 0.f;

        #pragma unroll
        for (int p = 0; p < 3; p++) {
            const uint32_t aOff = sb + ((p == 1) ? P4A_LO(buf) : P4A_HI(buf));
            const uint32_t wOff = sb + ((p == 2) ? P4W_LO : P4W_HI);
            #pragma unroll
            for (int ks = 0; ks < 8; ks++) {
                const uint32_t kb = (uint32_t)(ks * 32);
                uint32_t a0[4], a1[4];
                LDSM_X4(a0[0], a0[1], a0[2], a0[3], aOff + aRowRel + kb);
                LDSM_X4(a1[0], a1[1], a1[2], a1[3], aOff + aRowRel + 16 * TSTRIDE + kb);
                uint32_t b[2][4];
                #pragma unroll
                for (int j = 0; j < 2; j++)
                    LDSM_X4(b[j][0], b[j][1], b[j][2], b[j][3], wOff + bRow[j] + kb);
                #pragma unroll
                for (int j = 0; j < 2; j++) {
                    MMA16816(acc[0][j][0], a0, b[j][0], b[j][1]);
                    MMA16816(acc[1][j][0], a1, b[j][0], b[j][1]);
                    MMA16816(acc[0][j][1], a0, b[j][2], b[j][3]);
                    MMA16816(acc[1][j][1], a1, b[j][2], b[j][3]);
                }
            }
        }

        const int r0 = tile * 128;
        #pragma unroll
        for (int mt = 0; mt < 2; mt++) {
            int row = r0 + wm * 32 + mt * 16 + (lane >> 2);
            #pragma unroll
            for (int j = 0; j < 2; j++)
                #pragma unroll
                for (int h = 0; h < 2; h++) {
                    int col = colBase + j * 8 + h * 16;
                    if (col < 40) {
                        if (row < n)
                            *(float2*)&out[(size_t)row * 40 + col] =
                                make_float2(acc[mt][j][h][0], acc[mt][j][h][1]);
                        if (row + 8 < n)
                            *(float2*)&out[(size_t)(row + 8) * 40 + col] =
                                make_float2(acc[mt][j][h][2], acc[mt][j][h][3]);
                    }
                }
        }
        buf ^= 1;
    }
}

// ---------------- aggregation: TWO warps per node (64 features each, float2 lanes) ----
__global__ __launch_bounds__(256) void agg128(
    const float* __restrict__ t, const float* __restrict__ bias,
    __nv_bfloat16* __restrict__ ohi, __nv_bfloat16* __restrict__ olo)
{
    int gw = (blockIdx.x * blockDim.x + threadIdx.x) >> 5;   // 0 .. 2*N_NODES-1
    if (gw >= 2 * N_NODES) return;
    int node = gw >> 1;
    int half = gw & 1;
    int lane = threadIdx.x & 31;
    int fo = half * 32 + lane;                 // float2 index within 64-float2 row
    const float2* t2p = (const float2*)t;

    float dv = g_dinv[node];
    float self = dv * dv;
    float2 v = t2p[(size_t)node * 64 + fo];
    float ax = self * v.x, ay = self * v.y;

    int e0 = g_rowptr[node], e1 = g_rowptr[node + 1];
    for (int e = e0; e < e1; e++) {
        int s = g_eidx[e];
        float w = g_enorm[e];
        float2 u = t2p[(size_t)s * 64 + fo];
        ax += w * u.x; ay += w * u.y;
    }
    float2 bb = ((const float2*)bias)[fo];
    ax = fmaxf(ax + bb.x, 0.f);
    ay = fmaxf(ay + bb.y, 0.f);

    __nv_bfloat16 hx = __float2bfloat16(ax), hy = __float2bfloat16(ay);
    __nv_bfloat16 lx = __float2bfloat16(ax - __bfloat162float(hx));
    __nv_bfloat16 ly = __float2bfloat16(ay - __bfloat162float(hy));

    __nv_bfloat162 h2; h2.x = hx; h2.y = hy;
    __nv_bfloat162 l2; l2.x = lx; l2.y = ly;
    ((__nv_bfloat162*)ohi)[(size_t)node * 64 + fo] = h2;
    ((__nv_bfloat162*)olo)[(size_t)node * 64 + fo] = l2;
}

// ---------------- final aggregation (H=40) fused with log_softmax ----------------
__global__ __launch_bounds__(256) void agg40_lsm(
    const float* __restrict__ t, const float* __restrict__ bias,
    float* __restrict__ out)
{
    int warp = (blockIdx.x * blockDim.x + threadIdx.x) >> 5;
    if (warp >= N_NODES) return;
    int lane = threadIdx.x & 31;

    float dv = g_dinv[warp];
    float self = dv * dv;
    bool hi = (lane < 8);
    float a0 = self * t[warp * 40 + lane];
    float a1 = hi ? self * t[warp * 40 + 32 + lane] : 0.f;

    int e0 = g_rowptr[warp], e1 = g_rowptr[warp + 1];
    for (int e = e0; e < e1; e++) {
        int s = g_eidx[e];
        float w = g_enorm[e];
        a0 += w * t[(size_t)s * 40 + lane];
        if (hi) a1 += w * t[(size_t)s * 40 + 32 + lane];
    }
    a0 += bias[lane];
    if (hi) a1 += bias[32 + lane];

    float m = fmaxf(a0, hi ? a1 : -INFINITY);
    #pragma unroll
    for (int off = 16; off > 0; off >>= 1)
        m = fmaxf(m, __shfl_xor_sync(0xFFFFFFFFu, m, off));
    float s = expf(a0 - m) + (hi ? expf(a1 - m) : 0.f);
    #pragma unroll
    for (int off = 16; off > 0; off >>= 1)
        s += __shfl_xor_sync(0xFFFFFFFFu, s, off);
    float l = m + logf(s);

    out[warp * 40 + lane] = a0 - l;
    if (hi) out[warp * 40 + 32 + lane] = a1 - l;
}

// ---------------- launch ----------------
extern "C" void kernel_launch(void* const* d_in, const int* in_sizes, int n_in,
                              void* d_out, int out_size)
{
    const float* x  = (const float*)d_in[0];
    const int*   ei = (const int*)d_in[1];
    const float* W1 = (const float*)d_in[2];
    const float* b1 = (const float*)d_in[3];
    const float* W2 = (const float*)d_in[4];
    const float* b2 = (const float*)d_in[5];
    const float* W3 = (const float*)d_in[6];
    const float* b3 = (const float*)d_in[7];
    const float* W4 = (const float*)d_in[8];
    const float* b4 = (const float*)d_in[9];
    float* out = (float*)d_out;

    const int* src = ei;
    const int* dst = ei + N_EDGES;

    float* t;            cudaGetSymbolAddress((void**)&t,   g_t);
    __nv_bfloat16* hi;   cudaGetSymbolAddress((void**)&hi,  g_hi);
    __nv_bfloat16* lo;   cudaGetSymbolAddress((void**)&lo,  g_lo);
    __nv_bfloat16* whi;  cudaGetSymbolAddress((void**)&whi, g_whi);
    __nv_bfloat16* wlo;  cudaGetSymbolAddress((void**)&wlo, g_wlo);

    cudaFuncSetAttribute(gemm_pers,  cudaFuncAttributeMaxDynamicSharedMemorySize, SM_TOTAL);
    cudaFuncSetAttribute(gemm40_mma, cudaFuncAttributeMaxDynamicSharedMemorySize, SM40_TOTAL);

    static cudaStream_t s2 = nullptr;
    static cudaEvent_t evFork = nullptr, evJoin = nullptr;
    if (!s2) {
        cudaStreamCreateWithFlags(&s2, cudaStreamNonBlocking);
        cudaEventCreateWithFlags(&evFork, cudaEventDisableTiming);
        cudaEventCreateWithFlags(&evJoin, cudaEventDisableTiming);
    }

    const int NB_N = (N_NODES + 255) / 256;            // 391
    const int NB_E = (N_EDGES + 255) / 256;            // 2500
    const int NB_W = (N_NODES * 32 + 255) / 256;       // 12500 (1-warp-per-node kernels)
    const int NB_W2 = (N_NODES * 64 + 255) / 256;      // 25000 (2-warps-per-node agg128)
    const int NB_S1 = (N_NODES + 1023) / 1024;         // 98
    const int NB_CX = (N_NODES * 32 + 255) / 256;      // 12500
    const int NB_P = 148;

    // fork: graph-structure prep on s2, dense conversions + layer-1 GEMM on default
    cudaEventRecord(evFork, 0);
    cudaStreamWaitEvent(s2, evFork, 0);

    k_zero<<<NB_N, 256, 0, s2>>>();
    k_count<<<NB_E, 256, 0, s2>>>(dst);
    k_scan1<<<NB_S1, 1024, 0, s2>>>();
    k_scan2<<<1, 128, 0, s2>>>();
    k_scan3<<<NB_N, 256, 0, s2>>>();
    k_scatter<<<NB_E, 256, 0, s2>>>(src, dst);
    cudaEventRecord(evJoin, s2);

    k_convx<<<NB_CX, 256>>>(x);
    k_convw<<<64, 256>>>(W1, whi,             wlo);
    k_convw<<<64, 256>>>(W2, whi + 16384,     wlo + 16384);
    k_convw<<<64, 256>>>(W3, whi + 2 * 16384, wlo + 2 * 16384);
    k_convw4<<<32, 256>>>(W4);
    gemm_pers<<<NB_P, 256, SM_TOTAL>>>(hi, lo, whi, wlo, t, N_NODES);

    cudaStreamWaitEvent(0, evJoin, 0);

    agg128<<<NB_W2, 256>>>(t, b1, hi, lo);
    // layer 2
    gemm_pers<<<NB_P, 256, SM_TOTAL>>>(hi, lo, whi + 16384, wlo + 16384, t, N_NODES);
    agg128<<<NB_W2, 256>>>(t, b2, hi, lo);
    // layer 3
    gemm_pers<<<NB_P, 256, SM_TOTAL>>>(hi, lo, whi + 2 * 16384, wlo + 2 * 16384, t, N_NODES);
    agg128<<<NB_W2, 256>>>(t, b3, hi, lo);
    // layer 4 + log_softmax
    gemm40_mma<<<NB_P, 256, SM40_TOTAL>>>(hi, lo, t, N_NODES);
    agg40_lsm<<<NB_W, 256>>>(t, b4, out);
}

// round 17
// speedup vs baseline: 1.6226x; 1.6226x over previous
#include <cuda_runtime.h>
#include <cuda_bf16.h>
#include <math.h>
#include <stdint.h>

#define N_NODES 100000
#define N_EDGES 640000

// ---------------- device scratch ----------------
__device__ float g_t[N_NODES * 128];            // GEMM output (pre-aggregation)
__device__ __nv_bfloat16 g_hi[N_NODES * 128];   // activation hi
__device__ __nv_bfloat16 g_lo[N_NODES * 128];   // activation lo
__device__ int   g_cnt[N_NODES];
__device__ int   g_fill[N_NODES];
__device__ float g_dinv[N_NODES];
__device__ int   g_rowptr[N_NODES + 1];
__device__ int   g_bsum[128];
__device__ int   g_eidx[N_EDGES];
__device__ float g_enorm[N_EDGES];
__device__ __nv_bfloat16 g_whi[3 * 128 * 128];  // W1..W3 transposed hi  [n][k]
__device__ __nv_bfloat16 g_wlo[3 * 128 * 128];  // W1..W3 transposed lo  [n][k]
__device__ __nv_bfloat16 g_w4hi[64 * 128];      // W4 transposed+padded hi [n][k]
__device__ __nv_bfloat16 g_w4lo[64 * 128];      // W4 transposed+padded lo [n][k]

__device__ __forceinline__ uint32_t s2u(const void* p) {
    uint32_t a;
    asm("{ .reg .u64 t; cvta.to.shared.u64 t, %1; cvt.u32.u64 %0, t; }" : "=r"(a) : "l"(p));
    return a;
}

// ---------------- prep kernels ----------------
__global__ void k_zero() {
    int i = blockIdx.x * blockDim.x + threadIdx.x;
    if (i < N_NODES) { g_cnt[i] = 0; g_fill[i] = 0; }
}
__global__ void k_count(const int* __restrict__ dst) {
    int e = blockIdx.x * blockDim.x + threadIdx.x;
    if (e < N_EDGES) atomicAdd(&g_cnt[dst[e]], 1);
}

// multi-block scan; also computes dinv
__global__ __launch_bounds__(1024) void k_scan1() {
    int tid = threadIdx.x;
    int i = blockIdx.x * 1024 + tid;
    int v = (i < N_NODES) ? g_cnt[i] : 0;
    if (i < N_NODES) g_dinv[i] = rsqrtf((float)(v + 1));
    int lane = tid & 31, w = tid >> 5;
    int x = v;
    #pragma unroll
    for (int off = 1; off < 32; off <<= 1) {
        int t = __shfl_up_sync(0xFFFFFFFFu, x, off);
        if (lane >= off) x += t;
    }
    __shared__ int ws[32];
    if (lane == 31) ws[w] = x;
    __syncthreads();
    if (w == 0) {
        int y = ws[lane], o = y;
        #pragma unroll
        for (int off = 1; off < 32; off <<= 1) {
            int t = __shfl_up_sync(0xFFFFFFFFu, y, off);
            if (lane >= off) y += t;
        }
        ws[lane] = y - o;
    }
    __syncthreads();
    int incl = x + ws[w];
    if (i < N_NODES) g_rowptr[i] = incl - v;
    if (tid == 1023) g_bsum[blockIdx.x] = incl;
}
__global__ void k_scan2() {
    int tid = threadIdx.x;  // 128
    int v = (tid < 98) ? g_bsum[tid] : 0;
    int lane = tid & 31, w = tid >> 5;
    int x = v;
    #pragma unroll
    for (int off = 1; off < 32; off <<= 1) {
        int t = __shfl_up_sync(0xFFFFFFFFu, x, off);
        if (lane >= off) x += t;
    }
    __shared__ int ws[4];
    if (lane == 31) ws[w] = x;
    __syncthreads();
    __shared__ int wo[4];
    if (tid == 0) { int s = 0; for (int k = 0; k < 4; k++) { wo[k] = s; s += ws[k]; } }
    __syncthreads();
    if (tid < 98) g_bsum[tid] = x - v + wo[w];
}
__global__ void k_scan3() {
    int i = blockIdx.x * blockDim.x + threadIdx.x;
    if (i < N_NODES) g_rowptr[i] += g_bsum[i >> 10];
    if (i == 0) g_rowptr[N_NODES] = N_EDGES;
}
__global__ void k_scatter(const int* __restrict__ src, const int* __restrict__ dst) {
    int e = blockIdx.x * blockDim.x + threadIdx.x;
    if (e >= N_EDGES) return;
    int s = src[e], d = dst[e];
    int pos = g_rowptr[d] + atomicAdd(&g_fill[d], 1);
    g_eidx[pos] = s;
    g_enorm[pos] = g_dinv[s] * g_dinv[d];
}

// ---------------- precision-split conversion ----------------
__global__ void k_convx(const float* __restrict__ x) {
    int i = blockIdx.x * blockDim.x + threadIdx.x;
    if (i >= N_NODES * 32) return;
    float4 v = ((const float4*)x)[i];
    __nv_bfloat16 h0 = __float2bfloat16(v.x), h1 = __float2bfloat16(v.y);
    __nv_bfloat16 h2 = __float2bfloat16(v.z), h3 = __float2bfloat16(v.w);
    __nv_bfloat16 l0 = __float2bfloat16(v.x - __bfloat162float(h0));
    __nv_bfloat16 l1 = __float2bfloat16(v.y - __bfloat162float(h1));
    __nv_bfloat16 l2 = __float2bfloat16(v.z - __bfloat162float(h2));
    __nv_bfloat16 l3 = __float2bfloat16(v.w - __bfloat162float(h3));
    __nv_bfloat162* hp = (__nv_bfloat162*)g_hi;
    __nv_bfloat162* lp = (__nv_bfloat162*)g_lo;
    __nv_bfloat162 a; a.x = h0; a.y = h1; hp[i * 2] = a;
    __nv_bfloat162 b; b.x = h2; b.y = h3; hp[i * 2 + 1] = b;
    __nv_bfloat162 c; c.x = l0; c.y = l1; lp[i * 2] = c;
    __nv_bfloat162 d; d.x = l2; d.y = l3; lp[i * 2 + 1] = d;
}
// W [128k,128n] fp32 -> transposed [n][k] bf16 hi/lo
__global__ void k_convw(const float* __restrict__ W, __nv_bfloat16* __restrict__ hi,
                        __nv_bfloat16* __restrict__ lo) {
    int i = blockIdx.x * blockDim.x + threadIdx.x;  // 16384
    int n = i >> 7, k = i & 127;
    float v = W[k * 128 + n];
    __nv_bfloat16 h = __float2bfloat16(v);
    hi[i] = h;
    lo[i] = __float2bfloat16(v - __bfloat162float(h));
}
// W4 [128k,40n] fp32 -> transposed+padded [64 n][128 k] bf16 hi/lo
__global__ void k_convw4(const float* __restrict__ W) {
    int i = blockIdx.x * blockDim.x + threadIdx.x;  // 8192
    if (i >= 64 * 128) return;
    int n = i >> 7, k = i & 127;
    float v = (n < 40) ? W[k * 40 + n] : 0.f;
    __nv_bfloat16 h = __float2bfloat16(v);
    g_w4hi[i] = h;
    g_w4lo[i] = __float2bfloat16(v - __bfloat162float(h));
}

// ---------------- shared HMMA machinery ----------------
#define TSTRIDE 272

__device__ __forceinline__ void cp16(uint32_t saddr, const void* g) {
    asm volatile("cp.async.cg.shared.global [%0], [%1], 16;" :: "r"(saddr), "l"(g));
}
#define CP_COMMIT() asm volatile("cp.async.commit_group;" ::: "memory")
#define CP_WAIT0()  asm volatile("cp.async.wait_group 0;" ::: "memory")

#define LDSM_X4(r0, r1, r2, r3, addr) \
    asm volatile("ldmatrix.sync.aligned.m8n8.x4.shared.b16 {%0,%1,%2,%3}, [%4];" \
                 : "=r"(r0), "=r"(r1), "=r"(r2), "=r"(r3) : "r"(addr))

#define MMA16816(d, a, b0, b1) \
    asm volatile("mma.sync.aligned.m16n8k16.row.col.f32.bf16.bf16.f32 " \
                 "{%0,%1,%2,%3}, {%4,%5,%6,%7}, {%8,%9}, {%0,%1,%2,%3};" \
                 : "+f"((d)[0]), "+f"((d)[1]), "+f"((d)[2]), "+f"((d)[3]) \
                 : "r"((a)[0]), "r"((a)[1]), "r"((a)[2]), "r"((a)[3]), \
                   "r"(b0), "r"(b1))

// ---------------- persistent HMMA GEMM: [n,128]x[128,128], bf16 hi/lo split ----------
#define PW_HI 0
#define PW_LO 34816
#define PA_BASE 69632
#define PA_HI(b) (PA_BASE + (b) * 34816)
#define PA_LO(b) (PA_BASE + (b) * 34816 + 17408)
#define SM_TOTAL (PA_BASE + 2 * 34816)   // 139264 B

__device__ __forceinline__ void fill_A64(
    uint32_t sb, int buf, const __nv_bfloat16* Ahi, const __nv_bfloat16* Alo,
    int r0, int n, int tid)
{
    uint32_t bh = sb + PA_HI(buf), bl = sb + PA_LO(buf);
    #pragma unroll
    for (int l = 0; l < 4; l++) {
        int idx = tid + l * 256;
        int r = idx >> 4;
        int c = (idx & 15) << 4;
        int gr = r0 + r;
        if (gr >= n) gr = n - 1;
        int so = r * TSTRIDE + c;
        cp16(bh + so, (const char*)Ahi + (size_t)gr * 256 + c);
        cp16(bl + so, (const char*)Alo + (size_t)gr * 256 + c);
    }
}

__global__ __launch_bounds__(256) void gemm_pers(
    const __nv_bfloat16* __restrict__ Ahi, const __nv_bfloat16* __restrict__ Alo,
    const __nv_bfloat16* __restrict__ Whi, const __nv_bfloat16* __restrict__ Wlo,
    float* __restrict__ out, int n)
{
    extern __shared__ char smem[];
    const uint32_t sb = s2u(smem);
    const int tid = threadIdx.x;
    const int lane = tid & 31;
    const int wid = tid >> 5;
    const int wm = wid & 1;
    const int wn = wid >> 1;
    const int ntiles = (n + 63) >> 6;

    #pragma unroll
    for (int l = 0; l < 8; l++) {
        int idx = tid + l * 256;
        int r = idx >> 4;
        int c = (idx & 15) << 4;
        int so = r * TSTRIDE + c;
        cp16(sb + PW_HI + so, (const char*)Whi + (size_t)r * 256 + c);
        cp16(sb + PW_LO + so, (const char*)Wlo + (size_t)r * 256 + c);
    }
    int tile = blockIdx.x;
    if (tile < ntiles) fill_A64(sb, 0, Ahi, Alo, tile * 64, n, tid);
    CP_COMMIT();

    const int rA  = (lane & 7) + (((lane >> 3) & 1) << 3);
    const int kA8 = (lane >> 4) << 4;
    const int rBrow = (lane & 7) + ((lane >> 4) << 4);
    const int kB8   = (((lane >> 3) & 1) << 4);

    const uint32_t aRowRel = (uint32_t)((wm * 32 + rA) * TSTRIDE + kA8);
    uint32_t bRow[2];
    #pragma unroll
    for (int j = 0; j < 2; j++)
        bRow[j] = (uint32_t)((wn * 32 + j * 8 + rBrow) * TSTRIDE + kB8);
    const int colBase = wn * 32 + (lane & 3) * 2;

    int buf = 0;
    for (; tile < ntiles; tile += gridDim.x) {
        CP_WAIT0();
        __syncthreads();
        int next = tile + gridDim.x;
        if (next < ntiles) fill_A64(sb, buf ^ 1, Ahi, Alo, next * 64, n, tid);
        CP_COMMIT();

        float acc[2][2][2][4];
        #pragma unroll
        for (int mt = 0; mt < 2; mt++)
            #pragma unroll
            for (int j = 0; j < 2; j++)
                #pragma unroll
                for (int h = 0; h < 2; h++)
                    #pragma unroll
                    for (int q = 0; q < 4; q++) acc[mt][j][h][q] = 0.f;

        #pragma unroll
        for (int p = 0; p < 3; p++) {
            const uint32_t aOff = sb + ((p == 1) ? PA_LO(buf) : PA_HI(buf));
            const uint32_t wOff = sb + ((p == 2) ? PW_LO : PW_HI);
            #pragma unroll
            for (int ks = 0; ks < 8; ks++) {
                const uint32_t kb = (uint32_t)(ks * 32);
                uint32_t a0[4], a1[4];
                LDSM_X4(a0[0], a0[1], a0[2], a0[3], aOff + aRowRel + kb);
                LDSM_X4(a1[0], a1[1], a1[2], a1[3], aOff + aRowRel + 16 * TSTRIDE + kb);
                uint32_t b[2][4];
                #pragma unroll
                for (int j = 0; j < 2; j++)
                    LDSM_X4(b[j][0], b[j][1], b[j][2], b[j][3], wOff + bRow[j] + kb);
                #pragma unroll
                for (int j = 0; j < 2; j++) {
                    MMA16816(acc[0][j][0], a0, b[j][0], b[j][1]);
                    MMA16816(acc[1][j][0], a1, b[j][0], b[j][1]);
                    MMA16816(acc[0][j][1], a0, b[j][2], b[j][3]);
                    MMA16816(acc[1][j][1], a1, b[j][2], b[j][3]);
                }
            }
        }

        const int r0 = tile * 64;
        #pragma unroll
        for (int mt = 0; mt < 2; mt++) {
            int row = r0 + wm * 32 + mt * 16 + (lane >> 2);
            #pragma unroll
            for (int j = 0; j < 2; j++)
                #pragma unroll
                for (int h = 0; h < 2; h++) {
                    int col = colBase + j * 8 + h * 16;
                    if (row < n)
                        *(float2*)&out[(size_t)row * 128 + col] =
                            make_float2(acc[mt][j][h][0], acc[mt][j][h][1]);
                    if (row + 8 < n)
                        *(float2*)&out[(size_t)(row + 8) * 128 + col] =
                            make_float2(acc[mt][j][h][2], acc[mt][j][h][3]);
                }
        }
        buf ^= 1;
    }
}

// ---------------- persistent HMMA GEMM: [n,128]x[128,64(pad of 40)] ----------------
#define P4W_HI 0
#define P4W_LO 17408
#define P4A_BASE 34816
#define P4A_HI(b) (P4A_BASE + (b) * 69632)
#define P4A_LO(b) (P4A_BASE + (b) * 69632 + 34816)
#define SM40_TOTAL (P4A_BASE + 2 * 69632)   // 174080 B

__device__ __forceinline__ void fill_A128(
    uint32_t sb, int buf, const __nv_bfloat16* Ahi, const __nv_bfloat16* Alo,
    int r0, int n, int tid)
{
    uint32_t bh = sb + P4A_HI(buf), bl = sb + P4A_LO(buf);
    #pragma unroll
    for (int l = 0; l < 8; l++) {
        int idx = tid + l * 256;
        int r = idx >> 4;
        int c = (idx & 15) << 4;
        int gr = r0 + r;
        if (gr >= n) gr = n - 1;
        int so = r * TSTRIDE + c;
        cp16(bh + so, (const char*)Ahi + (size_t)gr * 256 + c);
        cp16(bl + so, (const char*)Alo + (size_t)gr * 256 + c);
    }
}

__global__ __launch_bounds__(256) void gemm40_mma(
    const __nv_bfloat16* __restrict__ Ahi, const __nv_bfloat16* __restrict__ Alo,
    float* __restrict__ out, int n)
{
    extern __shared__ char smem[];
    const uint32_t sb = s2u(smem);
    const int tid = threadIdx.x;
    const int lane = tid & 31;
    const int wid = tid >> 5;
    const int wm = wid & 3;
    const int wn = wid >> 2;
    const int ntiles = (n + 127) >> 7;

    #pragma unroll
    for (int l = 0; l < 4; l++) {
        int idx = tid + l * 256;
        int r = idx >> 4;
        int c = (idx & 15) << 4;
        int so = r * TSTRIDE + c;
        cp16(sb + P4W_HI + so, (const char*)g_w4hi + (size_t)r * 256 + c);
        cp16(sb + P4W_LO + so, (const char*)g_w4lo + (size_t)r * 256 + c);
    }
    int tile = blockIdx.x;
    if (tile < ntiles) fill_A128(sb, 0, Ahi, Alo, tile * 128, n, tid);
    CP_COMMIT();

    const int rA  = (lane & 7) + (((lane >> 3) & 1) << 3);
    const int kA8 = (lane >> 4) << 4;
    const int rBrow = (lane & 7) + ((lane >> 4) << 4);
    const int kB8   = (((lane >> 3) & 1) << 4);

    const uint32_t aRowRel = (uint32_t)((wm * 32 + rA) * TSTRIDE + kA8);
    uint32_t bRow[2];
    #pragma unroll
    for (int j = 0; j < 2; j++)
        bRow[j] = (uint32_t)((wn * 32 + j * 8 + rBrow) * TSTRIDE + kB8);
    const int colBase = wn * 32 + (lane & 3) * 2;

    int buf = 0;
    for (; tile < ntiles; tile += gridDim.x) {
        CP_WAIT0();
        __syncthreads();
        int next = tile + gridDim.x;
        if (next < ntiles) fill_A128(sb, buf ^ 1, Ahi, Alo, next * 128, n, tid);
        CP_COMMIT();

        float acc[2][2][2][4];
        #pragma unroll
        for (int mt = 0; mt < 2; mt++)
            #pragma unroll
            for (int j = 0; j < 2; j++)
                #pragma unroll
                for (int h = 0; h < 2; h++)
                    #pragma unroll
                    for (int q = 0; q < 4; q++) acc[mt][j][h][q] = 0.f;

        #pragma unroll
        for (int p = 0; p < 3; p++) {
            const uint32_t aOff = sb + ((p == 1) ? P4A_LO(buf) : P4A_HI(buf));
            const uint32_t wOff = sb + ((p == 2) ? P4W_LO : P4W_HI);
            #pragma unroll
            for (int ks = 0; ks < 8; ks++) {
                const uint32_t kb = (uint32_t)(ks * 32);
                uint32_t a0[4], a1[4];
                LDSM_X4(a0[0], a0[1], a0[2], a0[3], aOff + aRowRel + kb);
                LDSM_X4(a1[0], a1[1], a1[2], a1[3], aOff + aRowRel + 16 * TSTRIDE + kb);
                uint32_t b[2][4];
                #pragma unroll
                for (int j = 0; j < 2; j++)
                    LDSM_X4(b[j][0], b[j][1], b[j][2], b[j][3], wOff + bRow[j] + kb);
                #pragma unroll
                for (int j = 0; j < 2; j++) {
                    MMA16816(acc[0][j][0], a0, b[j][0], b[j][1]);
                    MMA16816(acc[1][j][0], a1, b[j][0], b[j][1]);
                    MMA16816(acc[0][j][1], a0, b[j][2], b[j][3]);
                    MMA16816(acc[1][j][1], a1, b[j][2], b[j][3]);
                }
            }
        }

        const int r0 = tile * 128;
        #pragma unroll
        for (int mt = 0; mt < 2; mt++) {
            int row = r0 + wm * 32 + mt * 16 + (lane >> 2);
            #pragma unroll
            for (int j = 0; j < 2; j++)
                #pragma unroll
                for (int h = 0; h < 2; h++) {
                    int col = colBase + j * 8 + h * 16;
                    if (col < 40) {
                        if (row < n)
                            *(float2*)&out[(size_t)row * 40 + col] =
                                make_float2(acc[mt][j][h][0], acc[mt][j][h][1]);
                        if (row + 8 < n)
                            *(float2*)&out[(size_t)(row + 8) * 40 + col] =
                                make_float2(acc[mt][j][h][2], acc[mt][j][h][3]);
                    }
                }
        }
        buf ^= 1;
    }
}

// ---------------- aggregation: warp per node, H=128, emits bf16 hi/lo ----------------
__global__ __launch_bounds__(256) void agg128(
    const float* __restrict__ t, const float* __restrict__ bias,
    __nv_bfloat16* __restrict__ ohi, __nv_bfloat16* __restrict__ olo)
{
    int warp = (blockIdx.x * blockDim.x + threadIdx.x) >> 5;
    if (warp >= N_NODES) return;
    int lane = threadIdx.x & 31;
    const float4* t4 = (const float4*)t;

    float dv = g_dinv[warp];
    float self = dv * dv;
    float4 v = t4[warp * 32 + lane];
    float ax = self * v.x, ay = self * v.y, az = self * v.z, aw = self * v.w;

    int e0 = g_rowptr[warp], e1 = g_rowptr[warp + 1];
    for (int e = e0; e < e1; e++) {
        int s = g_eidx[e];
        float w = g_enorm[e];
        float4 u = t4[(size_t)s * 32 + lane];
        ax += w * u.x; ay += w * u.y; az += w * u.z; aw += w * u.w;
    }
    float4 bb = ((const float4*)bias)[lane];
    ax = fmaxf(ax + bb.x, 0.f); ay = fmaxf(ay + bb.y, 0.f);
    az = fmaxf(az + bb.z, 0.f); aw = fmaxf(aw + bb.w, 0.f);

    __nv_bfloat16 hx = __float2bfloat16(ax), hy = __float2bfloat16(ay);
    __nv_bfloat16 hz = __float2bfloat16(az), hw = __float2bfloat16(aw);
    __nv_bfloat16 lx = __float2bfloat16(ax - __bfloat162float(hx));
    __nv_bfloat16 ly = __float2bfloat16(ay - __bfloat162float(hy));
    __nv_bfloat16 lz = __float2bfloat16(az - __bfloat162float(hz));
    __nv_bfloat16 lw = __float2bfloat16(aw - __bfloat162float(hw));

    __nv_bfloat162* hp = (__nv_bfloat162*)ohi;
    __nv_bfloat162* lp = (__nv_bfloat162*)olo;
    size_t base = (size_t)warp * 64 + lane * 2;
    __nv_bfloat162 a; a.x = hx; a.y = hy; hp[base] = a;
    __nv_bfloat162 b; b.x = hz; b.y = hw; hp[base + 1] = b;
    __nv_bfloat162 c; c.x = lx; c.y = ly; lp[base] = c;
    __nv_bfloat162 d; d.x = lz; d.y = lw; lp[base + 1] = d;
}

// ---------------- final aggregation (H=40) fused with log_softmax ----------------
__global__ __launch_bounds__(256) void agg40_lsm(
    const float* __restrict__ t, const float* __restrict__ bias,
    float* __restrict__ out)
{
    int warp = (blockIdx.x * blockDim.x + threadIdx.x) >> 5;
    if (warp >= N_NODES) return;
    int lane = threadIdx.x & 31;

    float dv = g_dinv[warp];
    float self = dv * dv;
    bool hi = (lane < 8);
    float a0 = self * t[warp * 40 + lane];
    float a1 = hi ? self * t[warp * 40 + 32 + lane] : 0.f;

    int e0 = g_rowptr[warp], e1 = g_rowptr[warp + 1];
    for (int e = e0; e < e1; e++) {
        int s = g_eidx[e];
        float w = g_enorm[e];
        a0 += w * t[(size_t)s * 40 + lane];
        if (hi) a1 += w * t[(size_t)s * 40 + 32 + lane];
    }
    a0 += bias[lane];
    if (hi) a1 += bias[32 + lane];

    float m = fmaxf(a0, hi ? a1 : -INFINITY);
    #pragma unroll
    for (int off = 16; off > 0; off >>= 1)
        m = fmaxf(m, __shfl_xor_sync(0xFFFFFFFFu, m, off));
    float s = expf(a0 - m) + (hi ? expf(a1 - m) : 0.f);
    #pragma unroll
    for (int off = 16; off > 0; off >>= 1)
        s += __shfl_xor_sync(0xFFFFFFFFu, s, off);
    float l = m + logf(s);

    out[warp * 40 + lane] = a0 - l;
    if (hi) out[warp * 40 + 32 + lane] = a1 - l;
}

// ---------------- launch ----------------
extern "C" void kernel_launch(void* const* d_in, const int* in_sizes, int n_in,
                              void* d_out, int out_size)
{
    const float* x  = (const float*)d_in[0];
    const int*   ei = (const int*)d_in[1];
    const float* W1 = (const float*)d_in[2];
    const float* b1 = (const float*)d_in[3];
    const float* W2 = (const float*)d_in[4];
    const float* b2 = (const float*)d_in[5];
    const float* W3 = (const float*)d_in[6];
    const float* b3 = (const float*)d_in[7];
    const float* W4 = (const float*)d_in[8];
    const float* b4 = (const float*)d_in[9];
    float* out = (float*)d_out;

    const int* src = ei;
    const int* dst = ei + N_EDGES;

    float* t;            cudaGetSymbolAddress((void**)&t,   g_t);
    __nv_bfloat16* hi;   cudaGetSymbolAddress((void**)&hi,  g_hi);
    __nv_bfloat16* lo;   cudaGetSymbolAddress((void**)&lo,  g_lo);
    __nv_bfloat16* whi;  cudaGetSymbolAddress((void**)&whi, g_whi);
    __nv_bfloat16* wlo;  cudaGetSymbolAddress((void**)&wlo, g_wlo);

    cudaFuncSetAttribute(gemm_pers,  cudaFuncAttributeMaxDynamicSharedMemorySize, SM_TOTAL);
    cudaFuncSetAttribute(gemm40_mma, cudaFuncAttributeMaxDynamicSharedMemorySize, SM40_TOTAL);

    static cudaStream_t s2 = nullptr;
    static cudaEvent_t evFork = nullptr, evJoin = nullptr;
    if (!s2) {
        cudaStreamCreateWithFlags(&s2, cudaStreamNonBlocking);
        cudaEventCreateWithFlags(&evFork, cudaEventDisableTiming);
        cudaEventCreateWithFlags(&evJoin, cudaEventDisableTiming);
    }

    const int NB_N = (N_NODES + 255) / 256;        // 391
    const int NB_E = (N_EDGES + 255) / 256;        // 2500
    const int NB_W = (N_NODES * 32 + 255) / 256;   // 12500
    const int NB_S1 = (N_NODES + 1023) / 1024;     // 98
    const int NB_CX = (N_NODES * 32 + 255) / 256;  // 12500
    const int NB_P = 148;                          // persistent: 1 CTA/SM

    // fork: graph-structure prep on s2, dense conversions + layer-1 GEMM on default
    cudaEventRecord(evFork, 0);
    cudaStreamWaitEvent(s2, evFork, 0);

    k_zero<<<NB_N, 256, 0, s2>>>();
    k_count<<<NB_E, 256, 0, s2>>>(dst);
    k_scan1<<<NB_S1, 1024, 0, s2>>>();             // also computes dinv
    k_scan2<<<1, 128, 0, s2>>>();
    k_scan3<<<NB_N, 256, 0, s2>>>();
    k_scatter<<<NB_E, 256, 0, s2>>>(src, dst);
    cudaEventRecord(evJoin, s2);

    // dense critical path: only the conversions gemm1 actually needs come first
    k_convx<<<NB_CX, 256>>>(x);
    k_convw<<<64, 256>>>(W1, whi, wlo);
    gemm_pers<<<NB_P, 256, SM_TOTAL>>>(hi, lo, whi, wlo, t, N_NODES);

    // later-layer weight conversions hidden behind gemm1/agg1 (same stream = ordered)
    k_convw<<<64, 256>>>(W2, whi + 16384,     wlo + 16384);
    k_convw<<<64, 256>>>(W3, whi + 2 * 16384, wlo + 2 * 16384);
    k_convw4<<<32, 256>>>(W4);

    // join: aggregation needs CSR from s2
    cudaStreamWaitEvent(0, evJoin, 0);

    agg128<<<NB_W, 256>>>(t, b1, hi, lo);
    // layer 2
    gemm_pers<<<NB_P, 256, SM_TOTAL>>>(hi, lo, whi + 16384, wlo + 16384, t, N_NODES);
    agg128<<<NB_W, 256>>>(t, b2, hi, lo);
    // layer 3
    gemm_pers<<<NB_P, 256, SM_TOTAL>>>(hi, lo, whi + 2 * 16384, wlo + 2 * 16384, t, N_NODES);
    agg128<<<NB_W, 256>>>(t, b3, hi, lo);
    // layer 4 + log_softmax
    gemm40_mma<<<NB_P, 256, SM40_TOTAL>>>(hi, lo, t, N_NODES);
    agg40_lsm<<<NB_W, 256>>>(t, b4, out);
}